// round 1
// baseline (speedup 1.0000x reference)
#include <cuda_runtime.h>
#include <cuda_bf16.h>
#include <cstdint>

// Problem constants
#define BB   8
#define NN   16384
#define CC   128
#define KNB  16
#define EDIM 132           // C + 4 (rel_pos 3 + dist_sq 1)
#define MTOT (BB * NN)     // 131072 points

// Scratch: per-point reduced features [M, 132]:
//   [0:128)  = mean_k neighbor_x
//   [128:131)= pos_i - mean_k pos_j
//   [131]    = mean_k dist_sq
__device__ float g_As[(size_t)MTOT * EDIM];

// ---------------------------------------------------------------------------
// Kernel 1: gather + reduce. One warp per point.
// Each lane owns 4 channels (float4); 16 neighbor rows are averaged.
// ---------------------------------------------------------------------------
__global__ void __launch_bounds__(256) gather_kernel(
    const float* __restrict__ x,
    const float* __restrict__ pos,
    const int*   __restrict__ idx)
{
    int p    = (blockIdx.x * blockDim.x + threadIdx.x) >> 5;   // point id
    int lane = threadIdx.x & 31;
    if (p >= MTOT) return;

    int b    = p >> 14;            // N = 16384 = 2^14
    int base = b << 14;            // batch row offset

    // lanes 0..15 hold the 16 neighbor indices; 16..31 duplicate (broadcast load)
    int j_l = __ldg(&idx[p * KNB + (lane & 15)]);

    float pix = __ldg(&pos[p * 3 + 0]);
    float piy = __ldg(&pos[p * 3 + 1]);
    float piz = __ldg(&pos[p * 3 + 2]);

    float4 acc = make_float4(0.f, 0.f, 0.f, 0.f);
    float srx = 0.f, sry = 0.f, srz = 0.f, sd = 0.f;

    #pragma unroll
    for (int k = 0; k < KNB; k++) {
        int jn  = __shfl_sync(0xffffffffu, j_l, k);
        int row = base + jn;
        const float4* xr = reinterpret_cast<const float4*>(x + (size_t)row * CC);
        float4 v = __ldg(&xr[lane]);
        float pjx = __ldg(&pos[row * 3 + 0]);
        float pjy = __ldg(&pos[row * 3 + 1]);
        float pjz = __ldg(&pos[row * 3 + 2]);
        acc.x += v.x; acc.y += v.y; acc.z += v.z; acc.w += v.w;
        float rx = pix - pjx, ry = piy - pjy, rz = piz - pjz;
        srx += rx; sry += ry; srz += rz;
        sd  += rx * rx + ry * ry + rz * rz;
    }

    const float s = 1.0f / 16.0f;
    float4 o = make_float4(acc.x * s, acc.y * s, acc.z * s, acc.w * s);
    *reinterpret_cast<float4*>(g_As + (size_t)p * EDIM + lane * 4) = o;
    if (lane == 0) {
        float* q = g_As + (size_t)p * EDIM + 128;
        q[0] = srx * s; q[1] = sry * s; q[2] = srz * s; q[3] = sd * s;
    }
}

// ---------------------------------------------------------------------------
// Kernel 2: fused GEMM + leaky_relu.
//   out[m, o] = lrelu( sum_{k<128} x[m,k] W_self[k,o]
//                    + sum_{e<132} As[m,e] W_edge[e,o] )
// Logical K = 260 padded to 264 (zeros). Tile: BM=128, BN=128, BK=8,
// 256 threads, 8x8 micro-tile per thread, double-buffered smem.
// ---------------------------------------------------------------------------
#define BK   8
#define NCH  33   // 264 / 8

__device__ __forceinline__ float4 loadA(const float* __restrict__ x,
                                        int m, int kk, int half)
{
    int k0 = kk * BK + half * 4;
    if (k0 < 128) return *reinterpret_cast<const float4*>(x + (size_t)m * CC + k0);
    if (k0 < 260) return *reinterpret_cast<const float4*>(g_As + (size_t)m * EDIM + (k0 - 128));
    return make_float4(0.f, 0.f, 0.f, 0.f);
}

__device__ __forceinline__ float4 loadW(const float4* __restrict__ ws4,
                                        const float4* __restrict__ we4,
                                        int kk, int wrow, int wcol)
{
    int k = kk * BK + wrow;
    if (k < 128) return ws4[k * 32 + wcol];
    if (k < 260) return we4[(k - 128) * 32 + wcol];
    return make_float4(0.f, 0.f, 0.f, 0.f);
}

__device__ __forceinline__ float lrelu(float v) {
    return v > 0.f ? v : 0.2f * v;
}

__global__ void __launch_bounds__(256) gemm_kernel(
    const float* __restrict__ x,
    const float* __restrict__ wself,
    const float* __restrict__ wedge,
    float*       __restrict__ out)
{
    // A tile stored k-major with stride 132 (=4*33, float4-aligned, conflict-free)
    __shared__ float As_s[2][BK * 132];
    __shared__ float Ws_s[2][BK * 128];

    int tid = threadIdx.x;
    int m0  = blockIdx.x * 128;

    int mrow = tid >> 1, half = tid & 1;   // A-tile loader mapping
    int wrow = tid >> 5, wcol = tid & 31;  // W-tile loader mapping

    const float4* ws4 = reinterpret_cast<const float4*>(wself);
    const float4* we4 = reinterpret_cast<const float4*>(wedge);

    // prologue: tile 0
    {
        float4 va = loadA(x, m0 + mrow, 0, half);
        float4 vw = loadW(ws4, we4, 0, wrow, wcol);
        float* d = &As_s[0][(half * 4) * 132 + mrow];
        d[0] = va.x; d[132] = va.y; d[264] = va.z; d[396] = va.w;
        *reinterpret_cast<float4*>(&Ws_s[0][wrow * 128 + wcol * 4]) = vw;
    }
    __syncthreads();

    int tm = tid >> 4, tn = tid & 15;      // 16x16 thread grid
    float acc[8][8];
    #pragma unroll
    for (int i = 0; i < 8; i++)
        #pragma unroll
        for (int j = 0; j < 8; j++) acc[i][j] = 0.f;

    for (int kk = 0; kk < NCH; kk++) {
        float4 na, nw;
        if (kk + 1 < NCH) {
            na = loadA(x, m0 + mrow, kk + 1, half);
            nw = loadW(ws4, we4, kk + 1, wrow, wcol);
        }
        int buf = kk & 1;
        #pragma unroll
        for (int kl = 0; kl < BK; kl++) {
            float a[8], bfr[8];
            const float* ap = &As_s[buf][kl * 132 + tm * 8];
            *reinterpret_cast<float4*>(a)     = *reinterpret_cast<const float4*>(ap);
            *reinterpret_cast<float4*>(a + 4) = *reinterpret_cast<const float4*>(ap + 4);
            // columns: tn*4..+3 and 64+tn*4..+3  (conflict-free LDS.128 pattern)
            const float* bp = &Ws_s[buf][kl * 128 + tn * 4];
            *reinterpret_cast<float4*>(bfr)     = *reinterpret_cast<const float4*>(bp);
            *reinterpret_cast<float4*>(bfr + 4) = *reinterpret_cast<const float4*>(bp + 64);
            #pragma unroll
            for (int i = 0; i < 8; i++)
                #pragma unroll
                for (int j = 0; j < 8; j++)
                    acc[i][j] += a[i] * bfr[j];
        }
        if (kk + 1 < NCH) {
            float* d = &As_s[buf ^ 1][(half * 4) * 132 + mrow];
            d[0] = na.x; d[132] = na.y; d[264] = na.z; d[396] = na.w;
            *reinterpret_cast<float4*>(&Ws_s[buf ^ 1][wrow * 128 + wcol * 4]) = nw;
            __syncthreads();
        }
    }

    // epilogue: leaky_relu + store
    #pragma unroll
    for (int i = 0; i < 8; i++) {
        int m = m0 + tm * 8 + i;
        float* op = out + (size_t)m * 128;
        float4 o0, o1;
        o0.x = lrelu(acc[i][0]); o0.y = lrelu(acc[i][1]);
        o0.z = lrelu(acc[i][2]); o0.w = lrelu(acc[i][3]);
        o1.x = lrelu(acc[i][4]); o1.y = lrelu(acc[i][5]);
        o1.z = lrelu(acc[i][6]); o1.w = lrelu(acc[i][7]);
        *reinterpret_cast<float4*>(op + tn * 4)      = o0;
        *reinterpret_cast<float4*>(op + 64 + tn * 4) = o1;
    }
}

// ---------------------------------------------------------------------------
extern "C" void kernel_launch(void* const* d_in, const int* in_sizes, int n_in,
                              void* d_out, int out_size)
{
    const float* x     = (const float*)d_in[0];
    const float* pos   = (const float*)d_in[1];
    const int*   idx   = (const int*)  d_in[2];
    const float* wself = (const float*)d_in[3];
    const float* wedge = (const float*)d_in[4];
    float* out = (float*)d_out;

    // one warp per point, 8 warps per block
    gather_kernel<<<MTOT / 8, 256>>>(x, pos, idx);
    // 131072 / 128 = 1024 tiles
    gemm_kernel<<<MTOT / 128, 256>>>(x, wself, wedge, out);
}

// round 4
// speedup vs baseline: 1.2744x; 1.2744x over previous
#include <cuda_runtime.h>
#include <cuda_bf16.h>
#include <cstdint>

// ---------------------------------------------------------------------------
// Problem constants
// ---------------------------------------------------------------------------
#define BB    8
#define NNPT  16384
#define CC    128
#define KNB   16
#define MTOT  (BB * NNPT)     // 131072 points
#define KPAD  288             // logical K = 260 (128 x | 128 mean_nx | 4 geo), padded

// Packed bf16 operands (hi/lo split), plain row-major.
__device__ __align__(16) __nv_bfloat16 g_Ah[(size_t)MTOT * KPAD];
__device__ __align__(16) __nv_bfloat16 g_Al[(size_t)MTOT * KPAD];
__device__ __align__(16) __nv_bfloat16 g_Bh[KPAD * 128];
__device__ __align__(16) __nv_bfloat16 g_Bl[KPAD * 128];

// ---------------------------------------------------------------------------
// Helpers
// ---------------------------------------------------------------------------
__device__ __forceinline__ uint32_t smem_u32(const void* p) {
    uint32_t a;
    asm("{ .reg .u64 t; cvta.to.shared.u64 t, %1; cvt.u32.u64 %0, t; }" : "=r"(a) : "l"(p));
    return a;
}
__device__ __forceinline__ void cp_async16(uint32_t dst, const void* src) {
    asm volatile("cp.async.ca.shared.global [%0], [%1], 16;" :: "r"(dst), "l"(src));
}
__device__ __forceinline__ uint32_t pk2(__nv_bfloat16 a, __nv_bfloat16 b) {
    __nv_bfloat162 t = __halves2bfloat162(a, b);
    return *reinterpret_cast<uint32_t*>(&t);
}
__device__ __forceinline__ void split_bf16(float v, __nv_bfloat16& h, __nv_bfloat16& l) {
    h = __float2bfloat16(v);
    l = __float2bfloat16(v - __bfloat162float(h));
}

// ---------------------------------------------------------------------------
// Kernel A: x -> Ah/Al columns [0,128). One thread per 8 channels.
// ---------------------------------------------------------------------------
__global__ void __launch_bounds__(256) xprep_kernel(const float* __restrict__ x) {
    int id = blockIdx.x * 256 + threadIdx.x;   // MTOT*16 threads
    int m = id >> 4, g = id & 15, k0 = g * 8;
    const float4* xr = reinterpret_cast<const float4*>(x + (size_t)m * CC + k0);
    float4 a = __ldg(xr), b = __ldg(xr + 1);
    float v[8] = {a.x, a.y, a.z, a.w, b.x, b.y, b.z, b.w};
    __nv_bfloat16 h[8], l[8];
#pragma unroll
    for (int i = 0; i < 8; i++) split_bf16(v[i], h[i], l[i]);
    uint4 uh = make_uint4(pk2(h[0], h[1]), pk2(h[2], h[3]), pk2(h[4], h[5]), pk2(h[6], h[7]));
    uint4 ul = make_uint4(pk2(l[0], l[1]), pk2(l[2], l[3]), pk2(l[4], l[5]), pk2(l[6], l[7]));
    size_t off = (size_t)m * KPAD + k0;
    *reinterpret_cast<uint4*>(g_Ah + off) = uh;
    *reinterpret_cast<uint4*>(g_Al + off) = ul;
}

// ---------------------------------------------------------------------------
// Kernel B: weights -> Bh/Bl [288][128]. One thread per element.
// ---------------------------------------------------------------------------
__global__ void __launch_bounds__(256) bprep_kernel(const float* __restrict__ ws,
                                                    const float* __restrict__ we) {
    int id = blockIdx.x * 256 + threadIdx.x;    // KPAD*128 threads
    if (id >= KPAD * 128) return;
    int k = id >> 7, n = id & 127;
    float v = 0.f;
    if (k < 128)      v = __ldg(&ws[k * 128 + n]);
    else if (k < 260) v = __ldg(&we[(k - 128) * 128 + n]);
    __nv_bfloat16 h, l;
    split_bf16(v, h, l);
    g_Bh[k * 128 + n] = h;
    g_Bl[k * 128 + n] = l;
}

// ---------------------------------------------------------------------------
// Kernel C: gather + reduce -> Ah/Al columns [128,288). One warp per point.
// ---------------------------------------------------------------------------
__global__ void __launch_bounds__(256) gather_kernel(
    const float* __restrict__ x,
    const float* __restrict__ pos,
    const int*   __restrict__ idx)
{
    int p    = (blockIdx.x * blockDim.x + threadIdx.x) >> 5;
    int lane = threadIdx.x & 31;
    if (p >= MTOT) return;

    int base = (p >> 14) << 14;   // batch row offset (N = 16384)

    int j_l = __ldg(&idx[p * KNB + (lane & 15)]);

    float pix = __ldg(&pos[p * 3 + 0]);
    float piy = __ldg(&pos[p * 3 + 1]);
    float piz = __ldg(&pos[p * 3 + 2]);

    float4 acc = make_float4(0.f, 0.f, 0.f, 0.f);
    float srx = 0.f, sry = 0.f, srz = 0.f, sd = 0.f;

#pragma unroll
    for (int k = 0; k < KNB; k++) {
        int jn  = __shfl_sync(0xffffffffu, j_l, k);
        int row = base + jn;
        const float4* xr = reinterpret_cast<const float4*>(x + (size_t)row * CC);
        float4 v = __ldg(&xr[lane]);
        float pjx = __ldg(&pos[row * 3 + 0]);
        float pjy = __ldg(&pos[row * 3 + 1]);
        float pjz = __ldg(&pos[row * 3 + 2]);
        acc.x += v.x; acc.y += v.y; acc.z += v.z; acc.w += v.w;
        float rx = pix - pjx, ry = piy - pjy, rz = piz - pjz;
        srx += rx; sry += ry; srz += rz;
        sd  += rx * rx + ry * ry + rz * rz;
    }

    const float s = 1.0f / 16.0f;

    // mean-x features -> columns 128 + lane*4 .. +3
    {
        float mv[4] = {acc.x * s, acc.y * s, acc.z * s, acc.w * s};
        __nv_bfloat16 h[4], l[4];
#pragma unroll
        for (int i = 0; i < 4; i++) split_bf16(mv[i], h[i], l[i]);
        size_t off = (size_t)p * KPAD + 128 + lane * 4;
        *reinterpret_cast<uint2*>(g_Ah + off) = make_uint2(pk2(h[0], h[1]), pk2(h[2], h[3]));
        *reinterpret_cast<uint2*>(g_Al + off) = make_uint2(pk2(l[0], l[1]), pk2(l[2], l[3]));
    }
    // columns [256,288): lane 0 writes {rel_pos_mean, dist_mean}; lanes 1..7 zero pad
    if (lane < 8) {
        float ev[4] = {0.f, 0.f, 0.f, 0.f};
        if (lane == 0) { ev[0] = srx * s; ev[1] = sry * s; ev[2] = srz * s; ev[3] = sd * s; }
        __nv_bfloat16 h[4], l[4];
#pragma unroll
        for (int i = 0; i < 4; i++) split_bf16(ev[i], h[i], l[i]);
        size_t off = (size_t)p * KPAD + 256 + lane * 4;
        *reinterpret_cast<uint2*>(g_Ah + off) = make_uint2(pk2(h[0], h[1]), pk2(h[2], h[3]));
        *reinterpret_cast<uint2*>(g_Al + off) = make_uint2(pk2(l[0], l[1]), pk2(l[2], l[3]));
    }
}

// ---------------------------------------------------------------------------
// Kernel D: warp-MMA bf16 GEMM (3-pass hi/lo) + leaky_relu.
// BM=BN=128, BK=32, 256 threads, warp grid 4(m) x 2(n), warp tile 32x64.
// 27 chunks = 3 passes {AhBh, AhBl, AlBh} x 9 k-chunks, double-buffered cp.async.
// ---------------------------------------------------------------------------
#define BM 128
#define BN 128
#define BK 32
#define ASTR 40    // A smem row stride (padded, conflict-free ldmatrix)
#define BSTR 136   // B smem row stride
#define NCHUNKS 27

__global__ void __launch_bounds__(256, 2) gemm_kernel(float* __restrict__ out) {
    __shared__ __nv_bfloat16 A_s[2][BM * ASTR];
    __shared__ __nv_bfloat16 B_s[2][BK * BSTR];

    int tid  = threadIdx.x;
    int m0   = blockIdx.x * BM;
    int wid  = tid >> 5, lane = tid & 31;
    int wm   = (wid & 3) * 32;       // warp m offset
    int wn   = (wid >> 2) * 64;      // warp n offset

    float acc[2][8][4];
#pragma unroll
    for (int t = 0; t < 2; t++)
#pragma unroll
        for (int j = 0; j < 8; j++)
#pragma unroll
            for (int r = 0; r < 4; r++) acc[t][j][r] = 0.f;

    auto load_chunk = [&](int q, int buf) {
        int pass = (q >= 18) ? 2 : (q >= 9 ? 1 : 0);
        int kb   = (q - pass * 9) * BK;
        const __nv_bfloat16* Ap = (pass < 2) ? g_Ah : g_Al;
        const __nv_bfloat16* Bp = (pass == 1) ? g_Bl : g_Bh;
        // A tile: 128 rows x 32 = 512 x 16B
#pragma unroll
        for (int i = 0; i < 2; i++) {
            int c = tid + i * 256;
            int row = c >> 2, seg = c & 3;
            cp_async16(smem_u32(&A_s[buf][row * ASTR + seg * 8]),
                       Ap + (size_t)(m0 + row) * KPAD + kb + seg * 8);
        }
        // B tile: 32 rows x 128 = 512 x 16B
#pragma unroll
        for (int i = 0; i < 2; i++) {
            int c = tid + i * 256;
            int row = c >> 4, seg = c & 15;
            cp_async16(smem_u32(&B_s[buf][row * BSTR + seg * 8]),
                       Bp + (size_t)(kb + row) * 128 + seg * 8);
        }
        asm volatile("cp.async.commit_group;" ::: "memory");
    };

    load_chunk(0, 0);

    for (int q = 0; q < NCHUNKS; q++) {
        if (q + 1 < NCHUNKS) {
            load_chunk(q + 1, (q + 1) & 1);
            asm volatile("cp.async.wait_group 1;" ::: "memory");
        } else {
            asm volatile("cp.async.wait_group 0;" ::: "memory");
        }
        __syncthreads();

        const __nv_bfloat16* As = A_s[q & 1];
        const __nv_bfloat16* Bs = B_s[q & 1];

#pragma unroll
        for (int s = 0; s < 2; s++) {           // two k16 steps per chunk
            uint32_t af[2][4];
#pragma unroll
            for (int t = 0; t < 2; t++) {
                uint32_t addr = smem_u32(As + (wm + t * 16 + (lane & 15)) * ASTR
                                            + s * 16 + (lane >> 4) * 8);
                asm volatile("ldmatrix.sync.aligned.m8n8.x4.shared.b16 {%0,%1,%2,%3}, [%4];"
                             : "=r"(af[t][0]), "=r"(af[t][1]), "=r"(af[t][2]), "=r"(af[t][3])
                             : "r"(addr));
            }
            uint32_t bf[8][2];
#pragma unroll
            for (int u = 0; u < 4; u++) {
                uint32_t addr = smem_u32(Bs + (s * 16 + (lane & 15)) * BSTR
                                            + wn + u * 16 + (lane >> 4) * 8);
                asm volatile("ldmatrix.sync.aligned.m8n8.x4.trans.shared.b16 {%0,%1,%2,%3}, [%4];"
                             : "=r"(bf[2 * u][0]), "=r"(bf[2 * u][1]),
                               "=r"(bf[2 * u + 1][0]), "=r"(bf[2 * u + 1][1])
                             : "r"(addr));
            }
#pragma unroll
            for (int t = 0; t < 2; t++)
#pragma unroll
                for (int j = 0; j < 8; j++) {
                    asm volatile(
                        "mma.sync.aligned.m16n8k16.row.col.f32.bf16.bf16.f32 "
                        "{%0,%1,%2,%3}, {%4,%5,%6,%7}, {%8,%9}, {%0,%1,%2,%3};"
                        : "+f"(acc[t][j][0]), "+f"(acc[t][j][1]),
                          "+f"(acc[t][j][2]), "+f"(acc[t][j][3])
                        : "r"(af[t][0]), "r"(af[t][1]), "r"(af[t][2]), "r"(af[t][3]),
                          "r"(bf[j][0]), "r"(bf[j][1]));
                }
        }
        __syncthreads();
    }

    // Epilogue: leaky_relu + direct global store (float2 per acc pair)
#pragma unroll
    for (int t = 0; t < 2; t++) {
        int row = m0 + wm + t * 16 + (lane >> 2);
#pragma unroll
        for (int j = 0; j < 8; j++) {
            int col = wn + j * 8 + (lane & 3) * 2;
            float v0 = acc[t][j][0], v1 = acc[t][j][1];
            float v2 = acc[t][j][2], v3 = acc[t][j][3];
            float2 o0 = make_float2(v0 > 0.f ? v0 : 0.2f * v0,
                                    v1 > 0.f ? v1 : 0.2f * v1);
            float2 o1 = make_float2(v2 > 0.f ? v2 : 0.2f * v2,
                                    v3 > 0.f ? v3 : 0.2f * v3);
            *reinterpret_cast<float2*>(out + (size_t)row * 128 + col)       = o0;
            *reinterpret_cast<float2*>(out + (size_t)(row + 8) * 128 + col) = o1;
        }
    }
}

// ---------------------------------------------------------------------------
extern "C" void kernel_launch(void* const* d_in, const int* in_sizes, int n_in,
                              void* d_out, int out_size)
{
    const float* x     = (const float*)d_in[0];
    const float* pos   = (const float*)d_in[1];
    const int*   idx   = (const int*)  d_in[2];
    const float* wself = (const float*)d_in[3];
    const float* wedge = (const float*)d_in[4];
    float* out = (float*)d_out;

    xprep_kernel<<<MTOT * 16 / 256, 256>>>(x);
    bprep_kernel<<<(KPAD * 128 + 255) / 256, 256>>>(wself, wedge);
    gather_kernel<<<MTOT / 8, 256>>>(x, pos, idx);
    gemm_kernel<<<MTOT / BM, 256>>>(out);
}

// round 5
// speedup vs baseline: 1.2763x; 1.0015x over previous
#include <cuda_runtime.h>
#include <cuda_bf16.h>
#include <cstdint>

// ---------------------------------------------------------------------------
// Problem constants
// ---------------------------------------------------------------------------
#define BB    8
#define NNPT  16384
#define CC    128
#define KNB   16
#define MTOT  (BB * NNPT)     // 131072 points
#define KPAD  288             // logical K = 260 (128 x | 128 mean_nx | 4 geo), padded

// Packed bf16 operands (hi/lo split), plain row-major.
__device__ __align__(16) __nv_bfloat16 g_Ah[(size_t)MTOT * KPAD];
__device__ __align__(16) __nv_bfloat16 g_Al[(size_t)MTOT * KPAD];
__device__ __align__(16) __nv_bfloat16 g_Bh[KPAD * 128];
__device__ __align__(16) __nv_bfloat16 g_Bl[KPAD * 128];

// ---------------------------------------------------------------------------
// Helpers
// ---------------------------------------------------------------------------
__device__ __forceinline__ uint32_t smem_u32(const void* p) {
    uint32_t a;
    asm("{ .reg .u64 t; cvta.to.shared.u64 t, %1; cvt.u32.u64 %0, t; }" : "=r"(a) : "l"(p));
    return a;
}
__device__ __forceinline__ void cp_async16(uint32_t dst, const void* src) {
    asm volatile("cp.async.ca.shared.global [%0], [%1], 16;" :: "r"(dst), "l"(src));
}
__device__ __forceinline__ uint32_t pk2(__nv_bfloat16 a, __nv_bfloat16 b) {
    __nv_bfloat162 t = __halves2bfloat162(a, b);
    return *reinterpret_cast<uint32_t*>(&t);
}
__device__ __forceinline__ void split_bf16(float v, __nv_bfloat16& h, __nv_bfloat16& l) {
    h = __float2bfloat16(v);
    l = __float2bfloat16(v - __bfloat162float(h));
}

// ---------------------------------------------------------------------------
// Kernel A: x -> Ah/Al columns [0,128). One thread per 8 channels.
// ---------------------------------------------------------------------------
__global__ void __launch_bounds__(256) xprep_kernel(const float* __restrict__ x) {
    int id = blockIdx.x * 256 + threadIdx.x;   // MTOT*16 threads
    int m = id >> 4, g = id & 15, k0 = g * 8;
    const float4* xr = reinterpret_cast<const float4*>(x + (size_t)m * CC + k0);
    float4 a = __ldg(xr), b = __ldg(xr + 1);
    float v[8] = {a.x, a.y, a.z, a.w, b.x, b.y, b.z, b.w};
    __nv_bfloat16 h[8], l[8];
#pragma unroll
    for (int i = 0; i < 8; i++) split_bf16(v[i], h[i], l[i]);
    uint4 uh = make_uint4(pk2(h[0], h[1]), pk2(h[2], h[3]), pk2(h[4], h[5]), pk2(h[6], h[7]));
    uint4 ul = make_uint4(pk2(l[0], l[1]), pk2(l[2], l[3]), pk2(l[4], l[5]), pk2(l[6], l[7]));
    size_t off = (size_t)m * KPAD + k0;
    *reinterpret_cast<uint4*>(g_Ah + off) = uh;
    *reinterpret_cast<uint4*>(g_Al + off) = ul;
}

// ---------------------------------------------------------------------------
// Kernel B: weights -> Bh/Bl [288][128]. One thread per element.
// ---------------------------------------------------------------------------
__global__ void __launch_bounds__(256) bprep_kernel(const float* __restrict__ ws,
                                                    const float* __restrict__ we) {
    int id = blockIdx.x * 256 + threadIdx.x;    // KPAD*128 threads
    if (id >= KPAD * 128) return;
    int k = id >> 7, n = id & 127;
    float v = 0.f;
    if (k < 128)      v = __ldg(&ws[k * 128 + n]);
    else if (k < 260) v = __ldg(&we[(k - 128) * 128 + n]);
    __nv_bfloat16 h, l;
    split_bf16(v, h, l);
    g_Bh[k * 128 + n] = h;
    g_Bl[k * 128 + n] = l;
}

// ---------------------------------------------------------------------------
// Kernel C: gather + reduce -> Ah/Al columns [128,288). One warp per point.
// ---------------------------------------------------------------------------
__global__ void __launch_bounds__(256) gather_kernel(
    const float* __restrict__ x,
    const float* __restrict__ pos,
    const int*   __restrict__ idx)
{
    int p    = (blockIdx.x * blockDim.x + threadIdx.x) >> 5;
    int lane = threadIdx.x & 31;
    if (p >= MTOT) return;

    int base = (p >> 14) << 14;   // batch row offset (N = 16384)

    int j_l = __ldg(&idx[p * KNB + (lane & 15)]);

    float pix = __ldg(&pos[p * 3 + 0]);
    float piy = __ldg(&pos[p * 3 + 1]);
    float piz = __ldg(&pos[p * 3 + 2]);

    float4 acc = make_float4(0.f, 0.f, 0.f, 0.f);
    float srx = 0.f, sry = 0.f, srz = 0.f, sd = 0.f;

#pragma unroll
    for (int k = 0; k < KNB; k++) {
        int jn  = __shfl_sync(0xffffffffu, j_l, k);
        int row = base + jn;
        const float4* xr = reinterpret_cast<const float4*>(x + (size_t)row * CC);
        float4 v = __ldg(&xr[lane]);
        float pjx = __ldg(&pos[row * 3 + 0]);
        float pjy = __ldg(&pos[row * 3 + 1]);
        float pjz = __ldg(&pos[row * 3 + 2]);
        acc.x += v.x; acc.y += v.y; acc.z += v.z; acc.w += v.w;
        float rx = pix - pjx, ry = piy - pjy, rz = piz - pjz;
        srx += rx; sry += ry; srz += rz;
        sd  += rx * rx + ry * ry + rz * rz;
    }

    const float s = 1.0f / 16.0f;

    // mean-x features -> columns 128 + lane*4 .. +3
    {
        float mv[4] = {acc.x * s, acc.y * s, acc.z * s, acc.w * s};
        __nv_bfloat16 h[4], l[4];
#pragma unroll
        for (int i = 0; i < 4; i++) split_bf16(mv[i], h[i], l[i]);
        size_t off = (size_t)p * KPAD + 128 + lane * 4;
        *reinterpret_cast<uint2*>(g_Ah + off) = make_uint2(pk2(h[0], h[1]), pk2(h[2], h[3]));
        *reinterpret_cast<uint2*>(g_Al + off) = make_uint2(pk2(l[0], l[1]), pk2(l[2], l[3]));
    }
    // columns [256,288): lane 0 writes {rel_pos_mean, dist_mean}; lanes 1..7 zero pad
    if (lane < 8) {
        float ev[4] = {0.f, 0.f, 0.f, 0.f};
        if (lane == 0) { ev[0] = srx * s; ev[1] = sry * s; ev[2] = srz * s; ev[3] = sd * s; }
        __nv_bfloat16 h[4], l[4];
#pragma unroll
        for (int i = 0; i < 4; i++) split_bf16(ev[i], h[i], l[i]);
        size_t off = (size_t)p * KPAD + 256 + lane * 4;
        *reinterpret_cast<uint2*>(g_Ah + off) = make_uint2(pk2(h[0], h[1]), pk2(h[2], h[3]));
        *reinterpret_cast<uint2*>(g_Al + off) = make_uint2(pk2(l[0], l[1]), pk2(l[2], l[3]));
    }
}

// ---------------------------------------------------------------------------
// Kernel D: warp-MMA bf16 GEMM (3-pass hi/lo) + leaky_relu.
// BM=BN=128, BK=32, 256 threads, warp grid 4(m) x 2(n), warp tile 32x64.
// 27 chunks = 3 passes {AhBh, AhBl, AlBh} x 9 k-chunks, double-buffered cp.async.
// ---------------------------------------------------------------------------
#define BM 128
#define BN 128
#define BK 32
#define ASTR 40    // A smem row stride (padded, conflict-free ldmatrix)
#define BSTR 136   // B smem row stride
#define NCHUNKS 27

__global__ void __launch_bounds__(256, 2) gemm_kernel(float* __restrict__ out) {
    __shared__ __nv_bfloat16 A_s[2][BM * ASTR];
    __shared__ __nv_bfloat16 B_s[2][BK * BSTR];

    int tid  = threadIdx.x;
    int m0   = blockIdx.x * BM;
    int wid  = tid >> 5, lane = tid & 31;
    int wm   = (wid & 3) * 32;       // warp m offset
    int wn   = (wid >> 2) * 64;      // warp n offset

    float acc[2][8][4];
#pragma unroll
    for (int t = 0; t < 2; t++)
#pragma unroll
        for (int j = 0; j < 8; j++)
#pragma unroll
            for (int r = 0; r < 4; r++) acc[t][j][r] = 0.f;

    auto load_chunk = [&](int q, int buf) {
        int pass = (q >= 18) ? 2 : (q >= 9 ? 1 : 0);
        int kb   = (q - pass * 9) * BK;
        const __nv_bfloat16* Ap = (pass < 2) ? g_Ah : g_Al;
        const __nv_bfloat16* Bp = (pass == 1) ? g_Bl : g_Bh;
        // A tile: 128 rows x 32 = 512 x 16B
#pragma unroll
        for (int i = 0; i < 2; i++) {
            int c = tid + i * 256;
            int row = c >> 2, seg = c & 3;
            cp_async16(smem_u32(&A_s[buf][row * ASTR + seg * 8]),
                       Ap + (size_t)(m0 + row) * KPAD + kb + seg * 8);
        }
        // B tile: 32 rows x 128 = 512 x 16B
#pragma unroll
        for (int i = 0; i < 2; i++) {
            int c = tid + i * 256;
            int row = c >> 4, seg = c & 15;
            cp_async16(smem_u32(&B_s[buf][row * BSTR + seg * 8]),
                       Bp + (size_t)(kb + row) * 128 + seg * 8);
        }
        asm volatile("cp.async.commit_group;" ::: "memory");
    };

    load_chunk(0, 0);

    for (int q = 0; q < NCHUNKS; q++) {
        if (q + 1 < NCHUNKS) {
            load_chunk(q + 1, (q + 1) & 1);
            asm volatile("cp.async.wait_group 1;" ::: "memory");
        } else {
            asm volatile("cp.async.wait_group 0;" ::: "memory");
        }
        __syncthreads();

        const __nv_bfloat16* As = A_s[q & 1];
        const __nv_bfloat16* Bs = B_s[q & 1];

#pragma unroll
        for (int s = 0; s < 2; s++) {           // two k16 steps per chunk
            uint32_t af[2][4];
#pragma unroll
            for (int t = 0; t < 2; t++) {
                uint32_t addr = smem_u32(As + (wm + t * 16 + (lane & 15)) * ASTR
                                            + s * 16 + (lane >> 4) * 8);
                asm volatile("ldmatrix.sync.aligned.m8n8.x4.shared.b16 {%0,%1,%2,%3}, [%4];"
                             : "=r"(af[t][0]), "=r"(af[t][1]), "=r"(af[t][2]), "=r"(af[t][3])
                             : "r"(addr));
            }
            uint32_t bf[8][2];
#pragma unroll
            for (int u = 0; u < 4; u++) {
                uint32_t addr = smem_u32(Bs + (s * 16 + (lane & 15)) * BSTR
                                            + wn + u * 16 + (lane >> 4) * 8);
                asm volatile("ldmatrix.sync.aligned.m8n8.x4.trans.shared.b16 {%0,%1,%2,%3}, [%4];"
                             : "=r"(bf[2 * u][0]), "=r"(bf[2 * u][1]),
                               "=r"(bf[2 * u + 1][0]), "=r"(bf[2 * u + 1][1])
                             : "r"(addr));
            }
#pragma unroll
            for (int t = 0; t < 2; t++)
#pragma unroll
                for (int j = 0; j < 8; j++) {
                    asm volatile(
                        "mma.sync.aligned.m16n8k16.row.col.f32.bf16.bf16.f32 "
                        "{%0,%1,%2,%3}, {%4,%5,%6,%7}, {%8,%9}, {%0,%1,%2,%3};"
                        : "+f"(acc[t][j][0]), "+f"(acc[t][j][1]),
                          "+f"(acc[t][j][2]), "+f"(acc[t][j][3])
                        : "r"(af[t][0]), "r"(af[t][1]), "r"(af[t][2]), "r"(af[t][3]),
                          "r"(bf[j][0]), "r"(bf[j][1]));
                }
        }
        __syncthreads();
    }

    // Epilogue: leaky_relu + direct global store (float2 per acc pair)
#pragma unroll
    for (int t = 0; t < 2; t++) {
        int row = m0 + wm + t * 16 + (lane >> 2);
#pragma unroll
        for (int j = 0; j < 8; j++) {
            int col = wn + j * 8 + (lane & 3) * 2;
            float v0 = acc[t][j][0], v1 = acc[t][j][1];
            float v2 = acc[t][j][2], v3 = acc[t][j][3];
            float2 o0 = make_float2(v0 > 0.f ? v0 : 0.2f * v0,
                                    v1 > 0.f ? v1 : 0.2f * v1);
            float2 o1 = make_float2(v2 > 0.f ? v2 : 0.2f * v2,
                                    v3 > 0.f ? v3 : 0.2f * v3);
            *reinterpret_cast<float2*>(out + (size_t)row * 128 + col)       = o0;
            *reinterpret_cast<float2*>(out + (size_t)(row + 8) * 128 + col) = o1;
        }
    }
}

// ---------------------------------------------------------------------------
extern "C" void kernel_launch(void* const* d_in, const int* in_sizes, int n_in,
                              void* d_out, int out_size)
{
    const float* x     = (const float*)d_in[0];
    const float* pos   = (const float*)d_in[1];
    const int*   idx   = (const int*)  d_in[2];
    const float* wself = (const float*)d_in[3];
    const float* wedge = (const float*)d_in[4];
    float* out = (float*)d_out;

    xprep_kernel<<<MTOT * 16 / 256, 256>>>(x);
    bprep_kernel<<<(KPAD * 128 + 255) / 256, 256>>>(wself, wedge);
    gather_kernel<<<MTOT / 8, 256>>>(x, pos, idx);
    gemm_kernel<<<MTOT / BM, 256>>>(out);
}

// round 6
// speedup vs baseline: 1.2765x; 1.0001x over previous
#include <cuda_runtime.h>
#include <cuda_bf16.h>
#include <cstdint>

// ---------------------------------------------------------------------------
// Problem constants
// ---------------------------------------------------------------------------
#define BB    8
#define NNPT  16384
#define CC    128
#define KNB   16
#define MTOT  (BB * NNPT)     // 131072 points
#define KPAD  288             // logical K = 260 (128 x | 128 mean_nx | 4 geo), padded

// Packed bf16 operands (hi/lo split), plain row-major.
__device__ __align__(16) __nv_bfloat16 g_Ah[(size_t)MTOT * KPAD];
__device__ __align__(16) __nv_bfloat16 g_Al[(size_t)MTOT * KPAD];
__device__ __align__(16) __nv_bfloat16 g_Bh[KPAD * 128];
__device__ __align__(16) __nv_bfloat16 g_Bl[KPAD * 128];

// ---------------------------------------------------------------------------
// Helpers
// ---------------------------------------------------------------------------
__device__ __forceinline__ uint32_t smem_u32(const void* p) {
    uint32_t a;
    asm("{ .reg .u64 t; cvta.to.shared.u64 t, %1; cvt.u32.u64 %0, t; }" : "=r"(a) : "l"(p));
    return a;
}
__device__ __forceinline__ void cp_async16(uint32_t dst, const void* src) {
    asm volatile("cp.async.ca.shared.global [%0], [%1], 16;" :: "r"(dst), "l"(src));
}
__device__ __forceinline__ uint32_t pk2(__nv_bfloat16 a, __nv_bfloat16 b) {
    __nv_bfloat162 t = __halves2bfloat162(a, b);
    return *reinterpret_cast<uint32_t*>(&t);
}
__device__ __forceinline__ void split_bf16(float v, __nv_bfloat16& h, __nv_bfloat16& l) {
    h = __float2bfloat16(v);
    l = __float2bfloat16(v - __bfloat162float(h));
}

// ---------------------------------------------------------------------------
// Kernel A: x -> Ah/Al columns [0,128). One thread per 8 channels.
// ---------------------------------------------------------------------------
__global__ void __launch_bounds__(256) xprep_kernel(const float* __restrict__ x) {
    int id = blockIdx.x * 256 + threadIdx.x;   // MTOT*16 threads
    int m = id >> 4, g = id & 15, k0 = g * 8;
    const float4* xr = reinterpret_cast<const float4*>(x + (size_t)m * CC + k0);
    float4 a = __ldg(xr), b = __ldg(xr + 1);
    float v[8] = {a.x, a.y, a.z, a.w, b.x, b.y, b.z, b.w};
    __nv_bfloat16 h[8], l[8];
#pragma unroll
    for (int i = 0; i < 8; i++) split_bf16(v[i], h[i], l[i]);
    uint4 uh = make_uint4(pk2(h[0], h[1]), pk2(h[2], h[3]), pk2(h[4], h[5]), pk2(h[6], h[7]));
    uint4 ul = make_uint4(pk2(l[0], l[1]), pk2(l[2], l[3]), pk2(l[4], l[5]), pk2(l[6], l[7]));
    size_t off = (size_t)m * KPAD + k0;
    *reinterpret_cast<uint4*>(g_Ah + off) = uh;
    *reinterpret_cast<uint4*>(g_Al + off) = ul;
}

// ---------------------------------------------------------------------------
// Kernel B: weights -> Bh/Bl [288][128]. One thread per element.
// ---------------------------------------------------------------------------
__global__ void __launch_bounds__(256) bprep_kernel(const float* __restrict__ ws,
                                                    const float* __restrict__ we) {
    int id = blockIdx.x * 256 + threadIdx.x;    // KPAD*128 threads
    if (id >= KPAD * 128) return;
    int k = id >> 7, n = id & 127;
    float v = 0.f;
    if (k < 128)      v = __ldg(&ws[k * 128 + n]);
    else if (k < 260) v = __ldg(&we[(k - 128) * 128 + n]);
    __nv_bfloat16 h, l;
    split_bf16(v, h, l);
    g_Bh[k * 128 + n] = h;
    g_Bl[k * 128 + n] = l;
}

// ---------------------------------------------------------------------------
// Kernel C: gather + reduce -> Ah/Al columns [128,288). One warp per point.
// ---------------------------------------------------------------------------
__global__ void __launch_bounds__(256) gather_kernel(
    const float* __restrict__ x,
    const float* __restrict__ pos,
    const int*   __restrict__ idx)
{
    int p    = (blockIdx.x * blockDim.x + threadIdx.x) >> 5;
    int lane = threadIdx.x & 31;
    if (p >= MTOT) return;

    int base = (p >> 14) << 14;   // batch row offset (N = 16384)

    int j_l = __ldg(&idx[p * KNB + (lane & 15)]);

    float pix = __ldg(&pos[p * 3 + 0]);
    float piy = __ldg(&pos[p * 3 + 1]);
    float piz = __ldg(&pos[p * 3 + 2]);

    float4 acc = make_float4(0.f, 0.f, 0.f, 0.f);
    float srx = 0.f, sry = 0.f, srz = 0.f, sd = 0.f;

#pragma unroll
    for (int k = 0; k < KNB; k++) {
        int jn  = __shfl_sync(0xffffffffu, j_l, k);
        int row = base + jn;
        const float4* xr = reinterpret_cast<const float4*>(x + (size_t)row * CC);
        float4 v = __ldg(&xr[lane]);
        float pjx = __ldg(&pos[row * 3 + 0]);
        float pjy = __ldg(&pos[row * 3 + 1]);
        float pjz = __ldg(&pos[row * 3 + 2]);
        acc.x += v.x; acc.y += v.y; acc.z += v.z; acc.w += v.w;
        float rx = pix - pjx, ry = piy - pjy, rz = piz - pjz;
        srx += rx; sry += ry; srz += rz;
        sd  += rx * rx + ry * ry + rz * rz;
    }

    const float s = 1.0f / 16.0f;

    // mean-x features -> columns 128 + lane*4 .. +3
    {
        float mv[4] = {acc.x * s, acc.y * s, acc.z * s, acc.w * s};
        __nv_bfloat16 h[4], l[4];
#pragma unroll
        for (int i = 0; i < 4; i++) split_bf16(mv[i], h[i], l[i]);
        size_t off = (size_t)p * KPAD + 128 + lane * 4;
        *reinterpret_cast<uint2*>(g_Ah + off) = make_uint2(pk2(h[0], h[1]), pk2(h[2], h[3]));
        *reinterpret_cast<uint2*>(g_Al + off) = make_uint2(pk2(l[0], l[1]), pk2(l[2], l[3]));
    }
    // columns [256,288): lane 0 writes {rel_pos_mean, dist_mean}; lanes 1..7 zero pad
    if (lane < 8) {
        float ev[4] = {0.f, 0.f, 0.f, 0.f};
        if (lane == 0) { ev[0] = srx * s; ev[1] = sry * s; ev[2] = srz * s; ev[3] = sd * s; }
        __nv_bfloat16 h[4], l[4];
#pragma unroll
        for (int i = 0; i < 4; i++) split_bf16(ev[i], h[i], l[i]);
        size_t off = (size_t)p * KPAD + 256 + lane * 4;
        *reinterpret_cast<uint2*>(g_Ah + off) = make_uint2(pk2(h[0], h[1]), pk2(h[2], h[3]));
        *reinterpret_cast<uint2*>(g_Al + off) = make_uint2(pk2(l[0], l[1]), pk2(l[2], l[3]));
    }
}

// ---------------------------------------------------------------------------
// Kernel D: warp-MMA bf16 GEMM (3-pass hi/lo) + leaky_relu.
// BM=BN=128, BK=32, 256 threads, warp grid 4(m) x 2(n), warp tile 32x64.
// 27 chunks = 3 passes {AhBh, AhBl, AlBh} x 9 k-chunks, double-buffered cp.async.
// ---------------------------------------------------------------------------
#define BM 128
#define BN 128
#define BK 32
#define ASTR 40    // A smem row stride (padded, conflict-free ldmatrix)
#define BSTR 136   // B smem row stride
#define NCHUNKS 27

__global__ void __launch_bounds__(256, 2) gemm_kernel(float* __restrict__ out) {
    __shared__ __nv_bfloat16 A_s[2][BM * ASTR];
    __shared__ __nv_bfloat16 B_s[2][BK * BSTR];

    int tid  = threadIdx.x;
    int m0   = blockIdx.x * BM;
    int wid  = tid >> 5, lane = tid & 31;
    int wm   = (wid & 3) * 32;       // warp m offset
    int wn   = (wid >> 2) * 64;      // warp n offset

    float acc[2][8][4];
#pragma unroll
    for (int t = 0; t < 2; t++)
#pragma unroll
        for (int j = 0; j < 8; j++)
#pragma unroll
            for (int r = 0; r < 4; r++) acc[t][j][r] = 0.f;

    auto load_chunk = [&](int q, int buf) {
        int pass = (q >= 18) ? 2 : (q >= 9 ? 1 : 0);
        int kb   = (q - pass * 9) * BK;
        const __nv_bfloat16* Ap = (pass < 2) ? g_Ah : g_Al;
        const __nv_bfloat16* Bp = (pass == 1) ? g_Bl : g_Bh;
        // A tile: 128 rows x 32 = 512 x 16B
#pragma unroll
        for (int i = 0; i < 2; i++) {
            int c = tid + i * 256;
            int row = c >> 2, seg = c & 3;
            cp_async16(smem_u32(&A_s[buf][row * ASTR + seg * 8]),
                       Ap + (size_t)(m0 + row) * KPAD + kb + seg * 8);
        }
        // B tile: 32 rows x 128 = 512 x 16B
#pragma unroll
        for (int i = 0; i < 2; i++) {
            int c = tid + i * 256;
            int row = c >> 4, seg = c & 15;
            cp_async16(smem_u32(&B_s[buf][row * BSTR + seg * 8]),
                       Bp + (size_t)(kb + row) * 128 + seg * 8);
        }
        asm volatile("cp.async.commit_group;" ::: "memory");
    };

    load_chunk(0, 0);

    for (int q = 0; q < NCHUNKS; q++) {
        if (q + 1 < NCHUNKS) {
            load_chunk(q + 1, (q + 1) & 1);
            asm volatile("cp.async.wait_group 1;" ::: "memory");
        } else {
            asm volatile("cp.async.wait_group 0;" ::: "memory");
        }
        __syncthreads();

        const __nv_bfloat16* As = A_s[q & 1];
        const __nv_bfloat16* Bs = B_s[q & 1];

#pragma unroll
        for (int s = 0; s < 2; s++) {           // two k16 steps per chunk
            uint32_t af[2][4];
#pragma unroll
            for (int t = 0; t < 2; t++) {
                uint32_t addr = smem_u32(As + (wm + t * 16 + (lane & 15)) * ASTR
                                            + s * 16 + (lane >> 4) * 8);
                asm volatile("ldmatrix.sync.aligned.m8n8.x4.shared.b16 {%0,%1,%2,%3}, [%4];"
                             : "=r"(af[t][0]), "=r"(af[t][1]), "=r"(af[t][2]), "=r"(af[t][3])
                             : "r"(addr));
            }
            uint32_t bf[8][2];
#pragma unroll
            for (int u = 0; u < 4; u++) {
                uint32_t addr = smem_u32(Bs + (s * 16 + (lane & 15)) * BSTR
                                            + wn + u * 16 + (lane >> 4) * 8);
                asm volatile("ldmatrix.sync.aligned.m8n8.x4.trans.shared.b16 {%0,%1,%2,%3}, [%4];"
                             : "=r"(bf[2 * u][0]), "=r"(bf[2 * u][1]),
                               "=r"(bf[2 * u + 1][0]), "=r"(bf[2 * u + 1][1])
                             : "r"(addr));
            }
#pragma unroll
            for (int t = 0; t < 2; t++)
#pragma unroll
                for (int j = 0; j < 8; j++) {
                    asm volatile(
                        "mma.sync.aligned.m16n8k16.row.col.f32.bf16.bf16.f32 "
                        "{%0,%1,%2,%3}, {%4,%5,%6,%7}, {%8,%9}, {%0,%1,%2,%3};"
                        : "+f"(acc[t][j][0]), "+f"(acc[t][j][1]),
                          "+f"(acc[t][j][2]), "+f"(acc[t][j][3])
                        : "r"(af[t][0]), "r"(af[t][1]), "r"(af[t][2]), "r"(af[t][3]),
                          "r"(bf[j][0]), "r"(bf[j][1]));
                }
        }
        __syncthreads();
    }

    // Epilogue: leaky_relu + direct global store (float2 per acc pair)
#pragma unroll
    for (int t = 0; t < 2; t++) {
        int row = m0 + wm + t * 16 + (lane >> 2);
#pragma unroll
        for (int j = 0; j < 8; j++) {
            int col = wn + j * 8 + (lane & 3) * 2;
            float v0 = acc[t][j][0], v1 = acc[t][j][1];
            float v2 = acc[t][j][2], v3 = acc[t][j][3];
            float2 o0 = make_float2(v0 > 0.f ? v0 : 0.2f * v0,
                                    v1 > 0.f ? v1 : 0.2f * v1);
            float2 o1 = make_float2(v2 > 0.f ? v2 : 0.2f * v2,
                                    v3 > 0.f ? v3 : 0.2f * v3);
            *reinterpret_cast<float2*>(out + (size_t)row * 128 + col)       = o0;
            *reinterpret_cast<float2*>(out + (size_t)(row + 8) * 128 + col) = o1;
        }
    }
}

// ---------------------------------------------------------------------------
extern "C" void kernel_launch(void* const* d_in, const int* in_sizes, int n_in,
                              void* d_out, int out_size)
{
    const float* x     = (const float*)d_in[0];
    const float* pos   = (const float*)d_in[1];
    const int*   idx   = (const int*)  d_in[2];
    const float* wself = (const float*)d_in[3];
    const float* wedge = (const float*)d_in[4];
    float* out = (float*)d_out;

    xprep_kernel<<<MTOT * 16 / 256, 256>>>(x);
    bprep_kernel<<<(KPAD * 128 + 255) / 256, 256>>>(wself, wedge);
    gather_kernel<<<MTOT / 8, 256>>>(x, pos, idx);
    gemm_kernel<<<MTOT / BM, 256>>>(out);
}